// round 3
// baseline (speedup 1.0000x reference)
#include <cuda_runtime.h>
#include <math.h>
#include <stdint.h>

// Problem dims
#define Bsz 16
#define Lsz 1024
#define DMv 512
#define DIv 1024
#define STv 16
#define DCv 4
#define RKv 32
#define ODv 128
#define MTOK (Bsz*Lsz)          // 16384 tokens
#define XPD (RKv + 2*STv)       // 64

// ---------------- scratch (device globals; no runtime allocation) ----------------
__device__ float    g_xz  [(size_t)MTOK * 2 * DIv];   // [m, 2048] : xin | z
__device__ float    g_xc  [(size_t)MTOK * DIv];       // conv+silu output
__device__ float    g_xdbl[(size_t)MTOK * XPD];       // [m, 64] : dt_in | B | C
__device__ float    g_dt  [(size_t)MTOK * DIv];       // softplus(dt)
__device__ uint32_t g_y   [(size_t)MTOK * DIv];       // gated scan output (tf32 bits)
__device__ float    g_out1[(size_t)MTOK * DMv];       // y @ W_out
__device__ float    g_part[256 * Bsz * ODv];          // split-K partials for FC
__device__ uint32_t g_xt  [(size_t)MTOK * DMv];       // x as tf32 bits
__device__ uint32_t g_Wint[(size_t)DMv * 2 * DIv];    // W_in as tf32 bits
__device__ uint32_t g_Wot [(size_t)DIv * DMv];        // W_out as tf32 bits

// ---------------- helpers ---------------------------------------------------------
__device__ __forceinline__ uint32_t f2tf32(float x) {
    uint32_t u;
    asm("cvt.rna.tf32.f32 %0, %1;" : "=r"(u) : "f"(x));
    return u;
}

__device__ __forceinline__ void mma_tf32(float* c, const uint32_t* a, const uint32_t* b) {
    asm volatile(
        "mma.sync.aligned.m16n8k8.row.col.f32.tf32.tf32.f32 "
        "{%0,%1,%2,%3},{%4,%5,%6,%7},{%8,%9},{%0,%1,%2,%3};\n"
        : "+f"(c[0]), "+f"(c[1]), "+f"(c[2]), "+f"(c[3])
        : "r"(a[0]), "r"(a[1]), "r"(a[2]), "r"(a[3]), "r"(b[0]), "r"(b[1]));
}

__device__ __forceinline__ void cp16(void* smem, const void* gmem) {
    uint32_t s = (uint32_t)__cvta_generic_to_shared(smem);
    asm volatile("cp.async.cg.shared.global [%0], [%1], 16;\n" :: "r"(s), "l"(gmem));
}
__device__ __forceinline__ void cp_commit() { asm volatile("cp.async.commit_group;\n"); }
template<int N> __device__ __forceinline__ void cp_wait() {
    asm volatile("cp.async.wait_group %0;\n" :: "n"(N));
}

// ---------------- pre-convert fp32 -> tf32 bits -----------------------------------
__global__ void cvt_tf32_k(const float* __restrict__ in, uint32_t* __restrict__ out, int n4) {
    int i = blockIdx.x * blockDim.x + threadIdx.x;
    if (i >= n4) return;
    float4 v = ((const float4*)in)[i];
    ((uint4*)out)[i] = make_uint4(f2tf32(v.x), f2tf32(v.y), f2tf32(v.z), f2tf32(v.w));
}

// =========================== pipelined tf32 tensor GEMM ===========================
// C[M,N] = A[M,K] @ B[K,N], operands pre-converted tf32 bits, fp32 out.
// 128x128x32 block tile; 8 warps x (64x32); 2-stage cp.async double buffer.
#define BM 128
#define BN 128
#define BKt 32
#define AST 36
#define BST 136
#define ASTAGE (BM*AST)      // 4608 u32
#define BSTAGE (BKt*BST)     // 4352 u32
#define GSMEM ((2*(ASTAGE+BSTAGE))*4)   // 71680 bytes

__global__ __launch_bounds__(256, 2)
void tf32gemm_k(const uint32_t* __restrict__ A, const uint32_t* __restrict__ B,
                float* __restrict__ C, int M, int N, int K) {
    extern __shared__ uint32_t sm[];
    uint32_t* As = sm;                 // 2 stages
    uint32_t* Bs = sm + 2 * ASTAGE;

    const int tid  = threadIdx.x;
    const int lane = tid & 31;
    const int warp = tid >> 5;
    const int wm   = warp >> 2;
    const int wn   = warp & 3;
    const int g    = lane >> 2;
    const int tq   = lane & 3;
    const int brow = blockIdx.y * BM;
    const int bcol = blockIdx.x * BN;

    float acc[4][4][4];
#pragma unroll
    for (int i = 0; i < 4; i++)
#pragma unroll
        for (int j = 0; j < 4; j++)
#pragma unroll
            for (int r = 0; r < 4; r++) acc[i][j][r] = 0.f;

    // stage loader
    auto load_stage = [&](int k0, int st) {
        uint32_t* as = As + st * ASTAGE;
        uint32_t* bs = Bs + st * BSTAGE;
#pragma unroll
        for (int i = 0; i < 4; i++) {
            int slot = tid + i * 256;              // 1024 slots of 16B
            int row = slot >> 3, kq = (slot & 7) * 4;
            cp16(&as[row * AST + kq], &A[(size_t)(brow + row) * K + k0 + kq]);
        }
#pragma unroll
        for (int i = 0; i < 4; i++) {
            int slot = tid + i * 256;
            int row = slot >> 5, nq = (slot & 31) * 4;
            cp16(&bs[row * BST + nq], &B[(size_t)(k0 + row) * N + bcol + nq]);
        }
    };

    const int nk = K / BKt;
    load_stage(0, 0);
    cp_commit();

    for (int it = 0; it < nk; it++) {
        if (it + 1 < nk) {
            load_stage((it + 1) * BKt, (it + 1) & 1);
            cp_commit();
            cp_wait<1>();
        } else {
            cp_wait<0>();
        }
        __syncthreads();

        const uint32_t* as = As + (it & 1) * ASTAGE;
        const uint32_t* bs = Bs + (it & 1) * BSTAGE;
#pragma unroll
        for (int kt = 0; kt < 4; kt++) {
            const int ks = kt * 8;
            uint32_t af[4][4], bf[4][2];
#pragma unroll
            for (int mm = 0; mm < 4; mm++) {
                int r0 = wm * 64 + mm * 16 + g;
                af[mm][0] = as[r0 * AST + ks + tq];
                af[mm][1] = as[(r0 + 8) * AST + ks + tq];
                af[mm][2] = as[r0 * AST + ks + tq + 4];
                af[mm][3] = as[(r0 + 8) * AST + ks + tq + 4];
            }
#pragma unroll
            for (int nn = 0; nn < 4; nn++) {
                int c0 = wn * 32 + nn * 8 + g;
                bf[nn][0] = bs[(ks + tq) * BST + c0];
                bf[nn][1] = bs[(ks + tq + 4) * BST + c0];
            }
#pragma unroll
            for (int mm = 0; mm < 4; mm++)
#pragma unroll
                for (int nn = 0; nn < 4; nn++)
                    mma_tf32(acc[mm][nn], af[mm], bf[nn]);
        }
        __syncthreads();   // protect stage reuse next iteration
    }

#pragma unroll
    for (int mm = 0; mm < 4; mm++) {
#pragma unroll
        for (int nn = 0; nn < 4; nn++) {
            int r = brow + wm * 64 + mm * 16 + g;
            int c = bcol + wn * 32 + nn * 8 + tq * 2;
            *(float2*)&C[(size_t)r * N + c]       = make_float2(acc[mm][nn][0], acc[mm][nn][1]);
            *(float2*)&C[(size_t)(r + 8) * N + c] = make_float2(acc[mm][nn][2], acc[mm][nn][3]);
        }
    }
}

// ---------------- generic fp32 SGEMM (skinny xproj GEMM) -------------------------
template<int TBM, int TBN, int TBK, int TM, int TN>
__global__ void sgemm_k(const float* __restrict__ A, const float* __restrict__ B,
                        float* __restrict__ C, int M, int N, int K) {
    __shared__ float As2[TBK][TBM];
    __shared__ float Bs2[TBK][TBN];
    constexpr int NT = (TBM / TM) * (TBN / TN);
    const int tid  = threadIdx.x;
    const int brow = blockIdx.y * TBM;
    const int bcol = blockIdx.x * TBN;
    const int tcol = (tid % (TBN / TN)) * TN;
    const int trow = (tid / (TBN / TN)) * TM;

    float acc[TM][TN];
#pragma unroll
    for (int i = 0; i < TM; i++)
#pragma unroll
        for (int j = 0; j < TN; j++) acc[i][j] = 0.f;

    for (int k0 = 0; k0 < K; k0 += TBK) {
#pragma unroll
        for (int i = tid; i < TBM * TBK / 4; i += NT) {
            int r = i / (TBK / 4), c = (i % (TBK / 4)) * 4;
            float4 v = *(const float4*)&A[(size_t)(brow + r) * K + k0 + c];
            As2[c + 0][r] = v.x; As2[c + 1][r] = v.y;
            As2[c + 2][r] = v.z; As2[c + 3][r] = v.w;
        }
#pragma unroll
        for (int i = tid; i < TBK * TBN / 4; i += NT) {
            int r = i / (TBN / 4), c = (i % (TBN / 4)) * 4;
            *(float4*)&Bs2[r][c] = *(const float4*)&B[(size_t)(k0 + r) * N + bcol + c];
        }
        __syncthreads();
#pragma unroll
        for (int kk = 0; kk < TBK; kk++) {
            float ra[TM], rb[TN];
#pragma unroll
            for (int i = 0; i < TM; i++) ra[i] = As2[kk][trow + i];
#pragma unroll
            for (int j = 0; j < TN; j++) rb[j] = Bs2[kk][tcol + j];
#pragma unroll
            for (int i = 0; i < TM; i++)
#pragma unroll
                for (int j = 0; j < TN; j++)
                    acc[i][j] = fmaf(ra[i], rb[j], acc[i][j]);
        }
        __syncthreads();
    }
#pragma unroll
    for (int i = 0; i < TM; i++)
#pragma unroll
        for (int j = 0; j < TN; j += 4)
            *(float4*)&C[(size_t)(brow + trow + i) * N + bcol + tcol + j] =
                make_float4(acc[i][j], acc[i][j + 1], acc[i][j + 2], acc[i][j + 3]);
}

// ---------------- depthwise causal conv (DC=4) + SiLU ----------------------------
__global__ void conv_silu_k(const float* __restrict__ cw, const float* __restrict__ cb) {
    int idx = blockIdx.x * blockDim.x + threadIdx.x;
    if (idx >= MTOK * DIv) return;
    int d = idx % DIv;
    int m = idx / DIv;
    int t = m % Lsz;
    float acc = cb[d];
#pragma unroll
    for (int j = 0; j < DCv; j++) {
        int tt = t + j - (DCv - 1);
        if (tt >= 0)
            acc = fmaf(g_xz[(size_t)(m + j - (DCv - 1)) * (2 * DIv) + d], cw[d * DCv + j], acc);
    }
    float s = 1.f / (1.f + __expf(-acc));
    g_xc[idx] = acc * s;
}

// ---------------- dt = softplus(xdbl[:, :RK] @ W_dt + b_dt), smem-tiled ----------
__device__ __forceinline__ float softplus_f(float x) {
    return (x > 20.f) ? x : log1pf(__expf(x));
}

__global__ void dt_k(const float* __restrict__ Wdt, const float* __restrict__ bdt) {
    __shared__ float sW[RKv * 256];
    __shared__ float sx[32 * RKv];
    const int tid = threadIdx.x;
    const int ch0 = blockIdx.x * 256;
    const int m0  = blockIdx.y * 32;
    const int cg  = tid & 31;
    const int tg  = tid >> 5;

#pragma unroll
    for (int j = 0; j < 8; j++) {
        int slot = tid + j * 256;
        int k = slot >> 6, c4 = (slot & 63) * 4;
        *(float4*)&sW[k * 256 + c4] = *(const float4*)&Wdt[(size_t)k * DIv + ch0 + c4];
    }
    {
        int tok = tid >> 3, k4 = (tid & 7) * 4;
        *(float4*)&sx[tok * RKv + k4] = *(const float4*)&g_xdbl[(size_t)(m0 + tok) * XPD + k4];
    }
    __syncthreads();

    float acc[4][8];
#pragma unroll
    for (int i = 0; i < 4; i++)
#pragma unroll
        for (int j = 0; j < 8; j++) acc[i][j] = bdt[ch0 + cg + 32 * j];

    for (int k = 0; k < RKv; k++) {
        float wv[8];
#pragma unroll
        for (int j = 0; j < 8; j++) wv[j] = sW[k * 256 + cg + 32 * j];
#pragma unroll
        for (int i = 0; i < 4; i++) {
            float xv = sx[(tg * 4 + i) * RKv + k];
#pragma unroll
            for (int j = 0; j < 8; j++) acc[i][j] = fmaf(xv, wv[j], acc[i][j]);
        }
    }
#pragma unroll
    for (int i = 0; i < 4; i++)
#pragma unroll
        for (int j = 0; j < 8; j++)
            g_dt[(size_t)(m0 + tg * 4 + i) * DIv + ch0 + cg + 32 * j] = softplus_f(acc[i][j]);
}

// ---------------- selective scan, 4 threads per chain, fused gate ----------------
// warp: 8 chains x 4 parts. part = lane>>3 owns states [4p, 4p+4).
// y written as tf32 bits (consumed only by the W_out GEMM).
__global__ void scan_k(const float* __restrict__ A_log, const float* __restrict__ Dp) {
    const int tid  = threadIdx.x;
    const int warp = (blockIdx.x * blockDim.x + tid) >> 5;   // 0..2047
    const int lane = tid & 31;
    const int part = lane >> 3;          // 0..3
    const int cidx = lane & 7;           // 0..7
    const int chain = warp * 8 + cidx;   // 0..16383
    const int b = chain / DIv, d = chain % DIv;
    const int s0 = part * 4;

    float A[4], h[4];
#pragma unroll
    for (int s = 0; s < 4; s++) {
        A[s] = -__expf(A_log[d * STv + s0 + s]);
        h[s] = 0.f;
    }
    float dp = Dp[d];

    for (int t = 0; t < Lsz; t++) {
        size_t m = (size_t)b * Lsz + t;
        float dtv = g_dt[m * DIv + d];
        float u   = g_xc[m * DIv + d];
        float zv  = g_xz[m * 2 * DIv + DIv + d];
        float4 Bv = *(const float4*)&g_xdbl[m * XPD + RKv + s0];
        float4 Cv = *(const float4*)&g_xdbl[m * XPD + RKv + STv + s0];

        float dtu = dtv * u;
        float accv;
        {
            float dA0 = __expf(dtv * A[0]);
            float dA1 = __expf(dtv * A[1]);
            float dA2 = __expf(dtv * A[2]);
            float dA3 = __expf(dtv * A[3]);
            h[0] = fmaf(h[0], dA0, dtu * Bv.x);
            h[1] = fmaf(h[1], dA1, dtu * Bv.y);
            h[2] = fmaf(h[2], dA2, dtu * Bv.z);
            h[3] = fmaf(h[3], dA3, dtu * Bv.w);
            accv = h[0] * Cv.x + h[1] * Cv.y + h[2] * Cv.z + h[3] * Cv.w;
        }
        accv += __shfl_xor_sync(0xffffffffu, accv, 8);
        accv += __shfl_xor_sync(0xffffffffu, accv, 16);
        if (part == 0) {
            float yv = fmaf(dp, u, accv);
            float sg = 1.f / (1.f + __expf(-zv));
            g_y[m * DIv + d] = f2tf32(yv * (zv * sg));
        }
    }
}

// ---------------- final FC: out[16,128] = out1.view(16, L*DM) @ W_fc + b_fc ------
__global__ void fc_partial_k(const float* __restrict__ Wfc) {
    __shared__ float sa[Bsz][128];
    const int KTOT = Lsz * DMv;
    const int KC   = KTOT / 256;
    int k0 = blockIdx.x * KC;
    int n  = threadIdx.x;
    float acc[Bsz];
#pragma unroll
    for (int m = 0; m < Bsz; m++) acc[m] = 0.f;

    for (int ks = 0; ks < KC; ks += 128) {
        __syncthreads();
#pragma unroll
        for (int m = 0; m < Bsz; m++)
            sa[m][n] = g_out1[(size_t)m * KTOT + k0 + ks + n];
        __syncthreads();
        for (int kk = 0; kk < 128; kk++) {
            float w = Wfc[(size_t)(k0 + ks + kk) * ODv + n];
#pragma unroll
            for (int m = 0; m < Bsz; m++)
                acc[m] = fmaf(sa[m][kk], w, acc[m]);
        }
    }
#pragma unroll
    for (int m = 0; m < Bsz; m++)
        g_part[blockIdx.x * (Bsz * ODv) + m * ODv + n] = acc[m];
}

__global__ void fc_reduce_k(const float* __restrict__ bfc, float* __restrict__ out) {
    int i = blockIdx.x * blockDim.x + threadIdx.x;
    if (i >= Bsz * ODv) return;
    int n = i % ODv;
    float acc = bfc[n];
    for (int c = 0; c < 256; c++) acc += g_part[c * (Bsz * ODv) + i];
    out[i] = acc;
}

// ---------------- launch ----------------------------------------------------------
extern "C" void kernel_launch(void* const* d_in, const int* in_sizes, int n_in,
                              void* d_out, int out_size) {
    const float* x       = (const float*)d_in[0];
    const float* W_in    = (const float*)d_in[1];
    const float* conv_w  = (const float*)d_in[2];
    const float* conv_b  = (const float*)d_in[3];
    const float* W_xproj = (const float*)d_in[4];
    const float* W_dt    = (const float*)d_in[5];
    const float* b_dt    = (const float*)d_in[6];
    const float* A_log   = (const float*)d_in[7];
    const float* Dp      = (const float*)d_in[8];
    const float* W_out   = (const float*)d_in[9];
    const float* W_fc    = (const float*)d_in[10];
    const float* b_fc    = (const float*)d_in[11];
    float* out = (float*)d_out;

    float *p_xz, *p_xc, *p_xdbl, *p_out1;
    uint32_t *p_y, *p_xt, *p_Wint, *p_Wot;
    cudaGetSymbolAddress((void**)&p_xz,   g_xz);
    cudaGetSymbolAddress((void**)&p_xc,   g_xc);
    cudaGetSymbolAddress((void**)&p_xdbl, g_xdbl);
    cudaGetSymbolAddress((void**)&p_y,    g_y);
    cudaGetSymbolAddress((void**)&p_out1, g_out1);
    cudaGetSymbolAddress((void**)&p_xt,   g_xt);
    cudaGetSymbolAddress((void**)&p_Wint, g_Wint);
    cudaGetSymbolAddress((void**)&p_Wot,  g_Wot);

    cudaFuncSetAttribute(tf32gemm_k, cudaFuncAttributeMaxDynamicSharedMemorySize, GSMEM);

    // 0) pre-convert operands to tf32 bits
    cvt_tf32_k<<<(MTOK * DMv / 4 + 255) / 256, 256>>>(x, p_xt, MTOK * DMv / 4);
    cvt_tf32_k<<<(DMv * 2 * DIv / 4 + 255) / 256, 256>>>(W_in, p_Wint, DMv * 2 * DIv / 4);
    cvt_tf32_k<<<(DIv * DMv / 4 + 255) / 256, 256>>>(W_out, p_Wot, DIv * DMv / 4);

    // 1) xz = x @ W_in   [16384,512]x[512,2048]  (tf32 tensor, pipelined)
    tf32gemm_k<<<dim3((2 * DIv) / BN, MTOK / BM), 256, GSMEM>>>(p_xt, p_Wint, p_xz, MTOK, 2 * DIv, DMv);

    // 2) xc = silu(causal depthwise conv(xin))
    conv_silu_k<<<(MTOK * DIv) / 256, 256>>>(conv_w, conv_b);

    // 3) x_dbl = xc @ W_xproj   [16384,1024]x[1024,64]  (fp32)
    sgemm_k<128, 64, 8, 8, 4><<<dim3(1, MTOK / 128), 256>>>(p_xc, W_xproj, p_xdbl, MTOK, XPD, DIv);

    // 4) dt = softplus(x_dbl[:, :32] @ W_dt + b_dt)
    dt_k<<<dim3(DIv / 256, MTOK / 32), 256>>>(W_dt, b_dt);

    // 5) selective scan + gate (writes tf32 y)
    scan_k<<<(4 * Bsz * DIv) / 128, 128>>>(A_log, Dp);

    // 6) out1 = y @ W_out   [16384,1024]x[1024,512]  (tf32 tensor, pipelined)
    tf32gemm_k<<<dim3(DMv / BN, MTOK / BM), 256, GSMEM>>>(p_y, p_Wot, p_out1, MTOK, DMv, DIv);

    // 7) final FC, split-K + deterministic reduce
    fc_partial_k<<<256, 128>>>(W_fc);
    fc_reduce_k<<<(Bsz * ODv + 127) / 128, 128>>>(b_fc, out);
}

// round 5
// speedup vs baseline: 2.1812x; 2.1812x over previous
#include <cuda_runtime.h>
#include <math.h>
#include <stdint.h>

// Problem dims
#define Bsz 16
#define Lsz 1024
#define DMv 512
#define DIv 1024
#define STv 16
#define DCv 4
#define RKv 32
#define ODv 128
#define MTOK (Bsz*Lsz)          // 16384 tokens
#define XPD (RKv + 2*STv)       // 64
#define NCH 32                  // scan chunks
#define CHL (Lsz/NCH)           // 32 steps per chunk
#define FCSPLIT 512

// ---------------- scratch (device globals; no runtime allocation) ----------------
__device__ float    g_xz  [(size_t)MTOK * 2 * DIv];
__device__ float    g_xc  [(size_t)MTOK * DIv];
__device__ float    g_xdbl[(size_t)MTOK * XPD];
__device__ float    g_dt  [(size_t)MTOK * DIv];
__device__ uint32_t g_y   [(size_t)MTOK * DIv];          // tf32 bits
__device__ float    g_out1[(size_t)MTOK * DMv];
__device__ float    g_part[FCSPLIT * Bsz * ODv];
__device__ uint32_t g_xt  [(size_t)MTOK * DMv];
__device__ uint32_t g_Wint[(size_t)DMv * 2 * DIv];
__device__ uint32_t g_Wot [(size_t)DIv * DMv];
__device__ float    g_hend[(size_t)Bsz * NCH * STv * DIv];  // [b][c][s][d]
__device__ float    g_hin [(size_t)Bsz * NCH * STv * DIv];  // [b][c][s][d]
__device__ float    g_dts [(size_t)Bsz * NCH * DIv];        // [b][c][d]

// ---------------- helpers ---------------------------------------------------------
__device__ __forceinline__ uint32_t f2tf32(float x) {
    uint32_t u;
    asm("cvt.rna.tf32.f32 %0, %1;" : "=r"(u) : "f"(x));
    return u;
}

__device__ __forceinline__ void mma_tf32(float* c, const uint32_t* a, const uint32_t* b) {
    asm volatile(
        "mma.sync.aligned.m16n8k8.row.col.f32.tf32.tf32.f32 "
        "{%0,%1,%2,%3},{%4,%5,%6,%7},{%8,%9},{%0,%1,%2,%3};\n"
        : "+f"(c[0]), "+f"(c[1]), "+f"(c[2]), "+f"(c[3])
        : "r"(a[0]), "r"(a[1]), "r"(a[2]), "r"(a[3]), "r"(b[0]), "r"(b[1]));
}

__device__ __forceinline__ void cp16(void* smem, const void* gmem) {
    uint32_t s = (uint32_t)__cvta_generic_to_shared(smem);
    asm volatile("cp.async.cg.shared.global [%0], [%1], 16;\n" :: "r"(s), "l"(gmem));
}
__device__ __forceinline__ void cp_commit() { asm volatile("cp.async.commit_group;\n"); }
template<int N> __device__ __forceinline__ void cp_wait() {
    asm volatile("cp.async.wait_group %0;\n" :: "n"(N));
}

// ---------------- pre-convert fp32 -> tf32 bits -----------------------------------
__global__ void cvt_tf32_k(const float* __restrict__ in, uint32_t* __restrict__ out, int n4) {
    int i = blockIdx.x * blockDim.x + threadIdx.x;
    if (i >= n4) return;
    float4 v = ((const float4*)in)[i];
    ((uint4*)out)[i] = make_uint4(f2tf32(v.x), f2tf32(v.y), f2tf32(v.z), f2tf32(v.w));
}

// =========================== pipelined tf32 tensor GEMM ===========================
#define BM 128
#define BN 128
#define BKt 32
#define AST 36
#define BST 136
#define ASTAGE (BM*AST)
#define BSTAGE (BKt*BST)
#define GSMEM ((2*(ASTAGE+BSTAGE))*4)

__global__ __launch_bounds__(256, 2)
void tf32gemm_k(const uint32_t* __restrict__ A, const uint32_t* __restrict__ B,
                float* __restrict__ C, int M, int N, int K) {
    extern __shared__ uint32_t sm[];
    uint32_t* As = sm;
    uint32_t* Bs = sm + 2 * ASTAGE;

    const int tid  = threadIdx.x;
    const int lane = tid & 31;
    const int warp = tid >> 5;
    const int wm   = warp >> 2;
    const int wn   = warp & 3;
    const int g    = lane >> 2;
    const int tq   = lane & 3;
    const int brow = blockIdx.y * BM;
    const int bcol = blockIdx.x * BN;

    float acc[4][4][4];
#pragma unroll
    for (int i = 0; i < 4; i++)
#pragma unroll
        for (int j = 0; j < 4; j++)
#pragma unroll
            for (int r = 0; r < 4; r++) acc[i][j][r] = 0.f;

    auto load_stage = [&](int k0, int st) {
        uint32_t* as = As + st * ASTAGE;
        uint32_t* bs = Bs + st * BSTAGE;
#pragma unroll
        for (int i = 0; i < 4; i++) {
            int slot = tid + i * 256;
            int row = slot >> 3, kq = (slot & 7) * 4;
            cp16(&as[row * AST + kq], &A[(size_t)(brow + row) * K + k0 + kq]);
        }
#pragma unroll
        for (int i = 0; i < 4; i++) {
            int slot = tid + i * 256;
            int row = slot >> 5, nq = (slot & 31) * 4;
            cp16(&bs[row * BST + nq], &B[(size_t)(k0 + row) * N + bcol + nq]);
        }
    };

    const int nk = K / BKt;
    load_stage(0, 0);
    cp_commit();

    for (int it = 0; it < nk; it++) {
        if (it + 1 < nk) {
            load_stage((it + 1) * BKt, (it + 1) & 1);
            cp_commit();
            cp_wait<1>();
        } else {
            cp_wait<0>();
        }
        __syncthreads();

        const uint32_t* as = As + (it & 1) * ASTAGE;
        const uint32_t* bs = Bs + (it & 1) * BSTAGE;
#pragma unroll
        for (int kt = 0; kt < 4; kt++) {
            const int ks = kt * 8;
            uint32_t af[4][4], bf[4][2];
#pragma unroll
            for (int mm = 0; mm < 4; mm++) {
                int r0 = wm * 64 + mm * 16 + g;
                af[mm][0] = as[r0 * AST + ks + tq];
                af[mm][1] = as[(r0 + 8) * AST + ks + tq];
                af[mm][2] = as[r0 * AST + ks + tq + 4];
                af[mm][3] = as[(r0 + 8) * AST + ks + tq + 4];
            }
#pragma unroll
            for (int nn = 0; nn < 4; nn++) {
                int c0 = wn * 32 + nn * 8 + g;
                bf[nn][0] = bs[(ks + tq) * BST + c0];
                bf[nn][1] = bs[(ks + tq + 4) * BST + c0];
            }
#pragma unroll
            for (int mm = 0; mm < 4; mm++)
#pragma unroll
                for (int nn = 0; nn < 4; nn++)
                    mma_tf32(acc[mm][nn], af[mm], bf[nn]);
        }
        __syncthreads();
    }

#pragma unroll
    for (int mm = 0; mm < 4; mm++) {
#pragma unroll
        for (int nn = 0; nn < 4; nn++) {
            int r = brow + wm * 64 + mm * 16 + g;
            int c = bcol + wn * 32 + nn * 8 + tq * 2;
            *(float2*)&C[(size_t)r * N + c]       = make_float2(acc[mm][nn][0], acc[mm][nn][1]);
            *(float2*)&C[(size_t)(r + 8) * N + c] = make_float2(acc[mm][nn][2], acc[mm][nn][3]);
        }
    }
}

// ---------------- fp32 SGEMM (xproj), 64x64x16 tiles, 256 CTAs -------------------
template<int TBM, int TBN, int TBK, int TM, int TN>
__global__ void sgemm_k(const float* __restrict__ A, const float* __restrict__ B,
                        float* __restrict__ C, int M, int N, int K) {
    __shared__ float As2[TBK][TBM];
    __shared__ float Bs2[TBK][TBN];
    constexpr int NT = (TBM / TM) * (TBN / TN);
    const int tid  = threadIdx.x;
    const int brow = blockIdx.y * TBM;
    const int bcol = blockIdx.x * TBN;
    const int tcol = (tid % (TBN / TN)) * TN;
    const int trow = (tid / (TBN / TN)) * TM;

    float acc[TM][TN];
#pragma unroll
    for (int i = 0; i < TM; i++)
#pragma unroll
        for (int j = 0; j < TN; j++) acc[i][j] = 0.f;

    for (int k0 = 0; k0 < K; k0 += TBK) {
#pragma unroll
        for (int i = tid; i < TBM * TBK / 4; i += NT) {
            int r = i / (TBK / 4), c = (i % (TBK / 4)) * 4;
            float4 v = *(const float4*)&A[(size_t)(brow + r) * K + k0 + c];
            As2[c + 0][r] = v.x; As2[c + 1][r] = v.y;
            As2[c + 2][r] = v.z; As2[c + 3][r] = v.w;
        }
#pragma unroll
        for (int i = tid; i < TBK * TBN / 4; i += NT) {
            int r = i / (TBN / 4), c = (i % (TBN / 4)) * 4;
            *(float4*)&Bs2[r][c] = *(const float4*)&B[(size_t)(k0 + r) * N + bcol + c];
        }
        __syncthreads();
#pragma unroll
        for (int kk = 0; kk < TBK; kk++) {
            float ra[TM], rb[TN];
#pragma unroll
            for (int i = 0; i < TM; i++) ra[i] = As2[kk][trow + i];
#pragma unroll
            for (int j = 0; j < TN; j++) rb[j] = Bs2[kk][tcol + j];
#pragma unroll
            for (int i = 0; i < TM; i++)
#pragma unroll
                for (int j = 0; j < TN; j++)
                    acc[i][j] = fmaf(ra[i], rb[j], acc[i][j]);
        }
        __syncthreads();
    }
#pragma unroll
    for (int i = 0; i < TM; i++)
#pragma unroll
        for (int j = 0; j < TN; j += 4)
            *(float4*)&C[(size_t)(brow + trow + i) * N + bcol + tcol + j] =
                make_float4(acc[i][j], acc[i][j + 1], acc[i][j + 2], acc[i][j + 3]);
}

// ---------------- depthwise causal conv (DC=4) + SiLU ----------------------------
__global__ void conv_silu_k(const float* __restrict__ cw, const float* __restrict__ cb) {
    int idx = blockIdx.x * blockDim.x + threadIdx.x;
    if (idx >= MTOK * DIv) return;
    int d = idx % DIv;
    int m = idx / DIv;
    int t = m % Lsz;
    float acc = cb[d];
#pragma unroll
    for (int j = 0; j < DCv; j++) {
        int tt = t + j - (DCv - 1);
        if (tt >= 0)
            acc = fmaf(g_xz[(size_t)(m + j - (DCv - 1)) * (2 * DIv) + d], cw[d * DCv + j], acc);
    }
    float s = 1.f / (1.f + __expf(-acc));
    g_xc[idx] = acc * s;
}

// ---------------- dt = softplus(xdbl[:, :RK] @ W_dt + b_dt) ----------------------
__device__ __forceinline__ float softplus_f(float x) {
    return (x > 20.f) ? x : log1pf(__expf(x));
}

__global__ void dt_k(const float* __restrict__ Wdt, const float* __restrict__ bdt) {
    __shared__ float sW[RKv * 256];
    __shared__ float sx[32 * RKv];
    const int tid = threadIdx.x;
    const int ch0 = blockIdx.x * 256;
    const int m0  = blockIdx.y * 32;
    const int cg  = tid & 31;
    const int tg  = tid >> 5;

#pragma unroll
    for (int j = 0; j < 8; j++) {
        int slot = tid + j * 256;
        int k = slot >> 6, c4 = (slot & 63) * 4;
        *(float4*)&sW[k * 256 + c4] = *(const float4*)&Wdt[(size_t)k * DIv + ch0 + c4];
    }
    {
        int tok = tid >> 3, k4 = (tid & 7) * 4;
        *(float4*)&sx[tok * RKv + k4] = *(const float4*)&g_xdbl[(size_t)(m0 + tok) * XPD + k4];
    }
    __syncthreads();

    float acc[4][8];
#pragma unroll
    for (int i = 0; i < 4; i++)
#pragma unroll
        for (int j = 0; j < 8; j++) acc[i][j] = bdt[ch0 + cg + 32 * j];

    for (int k = 0; k < RKv; k++) {
        float wv[8];
#pragma unroll
        for (int j = 0; j < 8; j++) wv[j] = sW[k * 256 + cg + 32 * j];
#pragma unroll
        for (int i = 0; i < 4; i++) {
            float xv = sx[(tg * 4 + i) * RKv + k];
#pragma unroll
            for (int j = 0; j < 8; j++) acc[i][j] = fmaf(xv, wv[j], acc[i][j]);
        }
    }
#pragma unroll
    for (int i = 0; i < 4; i++)
#pragma unroll
        for (int j = 0; j < 8; j++)
            g_dt[(size_t)(m0 + tg * 4 + i) * DIv + ch0 + cg + 32 * j] = softplus_f(acc[i][j]);
}

// ================= chunked parallel scan ==========================================
// Pass A: per (b,chunk,d) local scan with h0=0; store h_end[16] and S=sum(dt).
// grid (DIv/128, NCH, Bsz), block 128.
__global__ void scan_chunk_k(const float* __restrict__ A_log) {
    const int d = blockIdx.x * 128 + threadIdx.x;
    const int c = blockIdx.y;
    const int b = blockIdx.z;

    float A[STv], h[STv];
#pragma unroll
    for (int s = 0; s < STv; s++) {
        A[s] = -__expf(A_log[d * STv + s]);
        h[s] = 0.f;
    }
    float S = 0.f;
    const int t0 = c * CHL;
    for (int i = 0; i < CHL; i++) {
        size_t m = (size_t)b * Lsz + t0 + i;
        float dtv = g_dt[m * DIv + d];
        float u   = g_xc[m * DIv + d];
        S += dtv;
        float dtu = dtv * u;
        float4 B0 = *(const float4*)&g_xdbl[m * XPD + RKv + 0];
        float4 B1 = *(const float4*)&g_xdbl[m * XPD + RKv + 4];
        float4 B2 = *(const float4*)&g_xdbl[m * XPD + RKv + 8];
        float4 B3 = *(const float4*)&g_xdbl[m * XPD + RKv + 12];
        float Bv[STv];
        *(float4*)&Bv[0] = B0; *(float4*)&Bv[4] = B1;
        *(float4*)&Bv[8] = B2; *(float4*)&Bv[12] = B3;
#pragma unroll
        for (int s = 0; s < STv; s++)
            h[s] = fmaf(h[s], __expf(dtv * A[s]), dtu * Bv[s]);
    }
    size_t base = (((size_t)b * NCH + c) * STv) * DIv + d;
#pragma unroll
    for (int s = 0; s < STv; s++)
        g_hend[base + (size_t)s * DIv] = h[s];
    g_dts[((size_t)b * NCH + c) * DIv + d] = S;
}

// Pass B: per (b,s,d): sequential combine over chunks; store h_in per chunk.
// grid (DIv/128, STv, Bsz), block 128.
__global__ void scan_combine_k(const float* __restrict__ A_log) {
    const int d = blockIdx.x * 128 + threadIdx.x;
    const int s = blockIdx.y;
    const int b = blockIdx.z;
    const float Av = -__expf(A_log[d * STv + s]);

    float hin = 0.f;
    for (int c = 0; c < NCH; c++) {
        size_t idx = (((size_t)b * NCH + c) * STv + s) * DIv + d;
        g_hin[idx] = hin;
        float S  = g_dts[((size_t)b * NCH + c) * DIv + d];
        float lc = g_hend[idx];
        hin = fmaf(hin, __expf(Av * S), lc);
    }
}

// Pass C: per (b,chunk,d): rescan with correct h_in, fused gate, tf32 y out.
// grid (DIv/128, NCH, Bsz), block 128.
__global__ void scan_out_k(const float* __restrict__ A_log, const float* __restrict__ Dp) {
    const int d = blockIdx.x * 128 + threadIdx.x;
    const int c = blockIdx.y;
    const int b = blockIdx.z;

    float A[STv], h[STv];
#pragma unroll
    for (int s = 0; s < STv; s++)
        A[s] = -__expf(A_log[d * STv + s]);
    size_t base = (((size_t)b * NCH + c) * STv) * DIv + d;
#pragma unroll
    for (int s = 0; s < STv; s++)
        h[s] = g_hin[base + (size_t)s * DIv];
    const float dp = Dp[d];

    const int t0 = c * CHL;
    for (int i = 0; i < CHL; i++) {
        size_t m = (size_t)b * Lsz + t0 + i;
        float dtv = g_dt[m * DIv + d];
        float u   = g_xc[m * DIv + d];
        float zv  = g_xz[m * 2 * DIv + DIv + d];
        float BC[2 * STv];
#pragma unroll
        for (int q = 0; q < 8; q++)
            *(float4*)&BC[q * 4] = *(const float4*)&g_xdbl[m * XPD + RKv + q * 4];
        float dtu = dtv * u;
        float acc = 0.f;
#pragma unroll
        for (int s = 0; s < STv; s++) {
            h[s] = fmaf(h[s], __expf(dtv * A[s]), dtu * BC[s]);
            acc  = fmaf(h[s], BC[STv + s], acc);
        }
        float yv = fmaf(dp, u, acc);
        float sg = 1.f / (1.f + __expf(-zv));
        g_y[m * DIv + d] = f2tf32(yv * (zv * sg));
    }
}

// ---------------- final FC: split-K 512 + deterministic reduce -------------------
__global__ void fc_partial_k(const float* __restrict__ Wfc) {
    __shared__ float sa[Bsz][128];
    const int KTOT = Lsz * DMv;            // 524288
    const int KC   = KTOT / FCSPLIT;       // 1024
    int k0 = blockIdx.x * KC;
    int n  = threadIdx.x;                  // 128
    float acc[Bsz];
#pragma unroll
    for (int m = 0; m < Bsz; m++) acc[m] = 0.f;

    for (int ks = 0; ks < KC; ks += 128) {
        __syncthreads();
#pragma unroll
        for (int m = 0; m < Bsz; m++)
            sa[m][n] = g_out1[(size_t)m * KTOT + k0 + ks + n];
        __syncthreads();
#pragma unroll 4
        for (int kk = 0; kk < 128; kk++) {
            float w = Wfc[(size_t)(k0 + ks + kk) * ODv + n];
#pragma unroll
            for (int m = 0; m < Bsz; m++)
                acc[m] = fmaf(sa[m][kk], w, acc[m]);
        }
    }
#pragma unroll
    for (int m = 0; m < Bsz; m++)
        g_part[blockIdx.x * (Bsz * ODv) + m * ODv + n] = acc[m];
}

__global__ void fc_reduce_k(const float* __restrict__ bfc, float* __restrict__ out) {
    int i = blockIdx.x * blockDim.x + threadIdx.x;
    if (i >= Bsz * ODv) return;
    int n = i % ODv;
    float acc = bfc[n];
    for (int c = 0; c < FCSPLIT; c++) acc += g_part[c * (Bsz * ODv) + i];
    out[i] = acc;
}

// ---------------- launch ----------------------------------------------------------
extern "C" void kernel_launch(void* const* d_in, const int* in_sizes, int n_in,
                              void* d_out, int out_size) {
    const float* x       = (const float*)d_in[0];
    const float* W_in    = (const float*)d_in[1];
    const float* conv_w  = (const float*)d_in[2];
    const float* conv_b  = (const float*)d_in[3];
    const float* W_xproj = (const float*)d_in[4];
    const float* W_dt    = (const float*)d_in[5];
    const float* b_dt    = (const float*)d_in[6];
    const float* A_log   = (const float*)d_in[7];
    const float* Dp      = (const float*)d_in[8];
    const float* W_out   = (const float*)d_in[9];
    const float* W_fc    = (const float*)d_in[10];
    const float* b_fc    = (const float*)d_in[11];
    float* out = (float*)d_out;

    float *p_xz, *p_xc, *p_xdbl, *p_out1;
    uint32_t *p_y, *p_xt, *p_Wint, *p_Wot;
    cudaGetSymbolAddress((void**)&p_xz,   g_xz);
    cudaGetSymbolAddress((void**)&p_xc,   g_xc);
    cudaGetSymbolAddress((void**)&p_xdbl, g_xdbl);
    cudaGetSymbolAddress((void**)&p_y,    g_y);
    cudaGetSymbolAddress((void**)&p_out1, g_out1);
    cudaGetSymbolAddress((void**)&p_xt,   g_xt);
    cudaGetSymbolAddress((void**)&p_Wint, g_Wint);
    cudaGetSymbolAddress((void**)&p_Wot,  g_Wot);

    cudaFuncSetAttribute(tf32gemm_k, cudaFuncAttributeMaxDynamicSharedMemorySize, GSMEM);

    // 0) pre-convert operands to tf32 bits
    cvt_tf32_k<<<(MTOK * DMv / 4 + 255) / 256, 256>>>(x, p_xt, MTOK * DMv / 4);
    cvt_tf32_k<<<(DMv * 2 * DIv / 4 + 255) / 256, 256>>>(W_in, p_Wint, DMv * 2 * DIv / 4);
    cvt_tf32_k<<<(DIv * DMv / 4 + 255) / 256, 256>>>(W_out, p_Wot, DIv * DMv / 4);

    // 1) xz = x @ W_in  (tf32 tensor, pipelined)
    tf32gemm_k<<<dim3((2 * DIv) / BN, MTOK / BM), 256, GSMEM>>>(p_xt, p_Wint, p_xz, MTOK, 2 * DIv, DMv);

    // 2) xc = silu(conv(xin))
    conv_silu_k<<<(MTOK * DIv) / 256, 256>>>(conv_w, conv_b);

    // 3) x_dbl = xc @ W_xproj   (fp32, 256 CTAs)
    sgemm_k<64, 64, 16, 4, 4><<<dim3(1, MTOK / 64), 256>>>(p_xc, W_xproj, p_xdbl, MTOK, XPD, DIv);

    // 4) dt
    dt_k<<<dim3(DIv / 256, MTOK / 32), 256>>>(W_dt, b_dt);

    // 5) chunked parallel scan
    scan_chunk_k  <<<dim3(DIv / 128, NCH, Bsz), 128>>>(A_log);
    scan_combine_k<<<dim3(DIv / 128, STv, Bsz), 128>>>(A_log);
    scan_out_k    <<<dim3(DIv / 128, NCH, Bsz), 128>>>(A_log, Dp);

    // 6) out1 = y @ W_out  (tf32 tensor, pipelined)
    tf32gemm_k<<<dim3(DMv / BN, MTOK / BM), 256, GSMEM>>>(p_y, p_Wot, p_out1, MTOK, DMv, DIv);

    // 7) final FC
    fc_partial_k<<<FCSPLIT, 128>>>(W_fc);
    fc_reduce_k<<<(Bsz * ODv + 127) / 128, 128>>>(b_fc, out);
}